// round 1
// baseline (speedup 1.0000x reference)
#include <cuda_runtime.h>
#include <math.h>

// ---------------------------------------------------------------------------
// CFNO: patchify(16x16) -> FFT(256,ortho) -> complex linear(256->16) ->
//       IFFT(16,ortho).real -> 1x1 conv(16->16) -> GroupNorm(8,16)
//
// Entire linear chain folded into one real [256,16] matrix G + bias g0,
// precomputed on device each launch. Hot pass is y = p @ G (+g0), fp32 exact.
// ---------------------------------------------------------------------------

#define PI_D 3.141592653589793238462643383279502884

// Scratch (static device arrays; no allocations)
__device__ float g_G[4096];              // [256][16]
__device__ float g_g0[16];
__device__ float g_Y[8 * 16 * 128 * 128];// 8 MB intermediate, (b,e,h,w) layout
__device__ float g_psum[64 * 64];        // [b*8+g][block-in-batch]
__device__ float g_psq[64 * 64];
__device__ float g_mean[64];
__device__ float g_istd[64];

// ---- packed fp32x2 helpers (Blackwell f32x2 pipe: 2 FMAs / instr) ----
__device__ __forceinline__ unsigned long long pack2(float a, float b) {
    unsigned long long r;
    asm("mov.b64 %0, {%1, %2};" : "=l"(r) : "f"(a), "f"(b));
    return r;
}
__device__ __forceinline__ void unpack2(unsigned long long v, float& lo, float& hi) {
    asm("mov.b64 {%0, %1}, %2;" : "=f"(lo), "=f"(hi) : "l"(v));
}
__device__ __forceinline__ void fma2(unsigned long long& acc,
                                     unsigned long long a, unsigned long long b) {
    asm("fma.rn.f32x2 %0, %1, %2, %0;" : "+l"(acc) : "l"(a), "l"(b));
}

// ---------------------------------------------------------------------------
// Kernel 1: fold FFT + complex linear + IFFT.real + conv into G[256][16], g0.
//
//   MR[j,d] = sum_k ( wr[d,k] cos th + wi[d,k] sin th ),  th = 2pi j k / 256
//   MI[j,d] = sum_k ( wi[d,k] cos th - wr[d,k] sin th )
//   CR[d,e] = sum_m cw[e,m] cos(2pi d m/16),  CI likewise with sin
//   G[j,e]  = (1/64) sum_d ( MR CR - MI CI )
//   g0[e]   = sum_m cw[e,m] * (1/4) sum_d ( br cos - bi sin ) + cb[e]
//
// Grid: 16 blocks x 256 threads; block handles j in [16*blockIdx, +16).
// ---------------------------------------------------------------------------
__global__ void precompute_kernel(const float* __restrict__ wr, const float* __restrict__ wi,
                                  const float* __restrict__ br, const float* __restrict__ bi,
                                  const float* __restrict__ cw, const float* __restrict__ cb) {
    __shared__ float cosT[256], sinT[256];
    __shared__ float swr[16 * 257], swi[16 * 257];  // pitch 257: conflict-free column reads
    __shared__ float sCR[256], sCI[256];            // [d][e]
    __shared__ float sMR[256], sMI[256];            // [jl][d]
    const int tid = threadIdx.x;

    {   // high-accuracy twiddle table
        double s, c;
        sincos(2.0 * PI_D * (double)tid / 256.0, &s, &c);
        cosT[tid] = (float)c; sinT[tid] = (float)s;
    }
    for (int i = tid; i < 4096; i += 256) {
        int d = i >> 8, k = i & 255;
        swr[d * 257 + k] = wr[i];
        swi[d * 257 + k] = wi[i];
    }
    __syncthreads();

    const int hi4 = tid >> 4, lo4 = tid & 15;
    {   // CR/CI: d = hi4, e = lo4
        float cr = 0.f, ci = 0.f;
#pragma unroll
        for (int m = 0; m < 16; m++) {
            int t = ((hi4 * m) & 15) << 4;   // angle 2pi*(d*m mod 16)/16
            float w = cw[lo4 * 16 + m];
            cr += w * cosT[t];
            ci += w * sinT[t];
        }
        sCR[hi4 * 16 + lo4] = cr; sCI[hi4 * 16 + lo4] = ci;
    }
    {   // MR/MI: jl = hi4, d = lo4
        const int jl = hi4, d = lo4;
        const int j = (blockIdx.x << 4) + jl;
        const float* a  = swr + d * 257;
        const float* bb = swi + d * 257;
        float mr = 0.f, mi = 0.f;
        int t = 0;                           // t = j*k mod 256, incrementally
        for (int k = 0; k < 256; k++) {
            float c = cosT[t], s = sinT[t];
            float av = a[k], bv = bb[k];
            mr += av * c + bv * s;
            mi += bv * c - av * s;
            t = (t + j) & 255;
        }
        sMR[jl * 16 + d] = mr; sMI[jl * 16 + d] = mi;
    }
    __syncthreads();
    {   // G[j][e]
        const int jl = hi4, e = lo4;
        const int j = (blockIdx.x << 4) + jl;
        float g = 0.f;
#pragma unroll
        for (int d = 0; d < 16; d++)
            g += sMR[jl * 16 + d] * sCR[d * 16 + e] - sMI[jl * 16 + d] * sCI[d * 16 + e];
        g_G[j * 16 + e] = g * (1.0f / 64.0f);
    }
    if (blockIdx.x == 0 && tid < 16) {       // fused bias
        float acc = cb[tid];
        for (int m = 0; m < 16; m++) {
            float b0 = 0.f;
            for (int d = 0; d < 16; d++) {
                int t = ((d * m) & 15) << 4;
                b0 += br[d] * cosT[t] - bi[d] * sinT[t];
            }
            acc += cw[tid * 16 + m] * b0 * 0.25f;
        }
        g_g0[tid] = acc;
    }
}

// ---------------------------------------------------------------------------
// Kernel 2 (hot): y = p @ G + g0 for all 131072 patches + GroupNorm partials.
// Block = 128 threads, handles 2 patch-rows (256 patches); thread t owns
// patch wi=t in both rows (amortizes broadcast G loads over 2 patches).
// Streams x rows through a transposed smem tile (conflict-free reads).
// ---------------------------------------------------------------------------
__global__ void __launch_bounds__(128) main_kernel(const float* __restrict__ x) {
    __shared__ __align__(16) float sG[4096];
    __shared__ float sX0[16][129];
    __shared__ float sX1[16][129];
    __shared__ float sred[4][16];
    __shared__ float sg0[16];
    const int tid = threadIdx.x;
    const int pr  = blockIdx.x;        // 0..511
    const int b   = pr >> 6;
    const int hp  = pr & 63;           // pair-row index; hi0 = 2*hp

    for (int i = tid; i < 4096; i += 128) sG[i] = g_G[i];
    if (tid < 16) sg0[tid] = g_g0[tid];

    unsigned long long acc0[8], acc1[8];
#pragma unroll
    for (int i = 0; i < 8; i++) { acc0[i] = 0ull; acc1[i] = 0ull; }

    const float* xb = x + (((size_t)b) << 22) + (((size_t)hp) << 16);
    __syncthreads();

    for (int s1 = 0; s1 < 16; s1++) {
        const float4* r0 = (const float4*)(xb + s1 * 2048);
        const float4* r1 = (const float4*)(xb + (s1 + 16) * 2048);
#pragma unroll
        for (int k2 = 0; k2 < 4; k2++) {
            int i4 = tid + (k2 << 7);
            float4 f0 = r0[i4];
            float4 f1 = r1[i4];
            int t  = i4 >> 2;
            int s2 = (i4 & 3) << 2;
            sX0[s2 + 0][t] = f0.x; sX0[s2 + 1][t] = f0.y;
            sX0[s2 + 2][t] = f0.z; sX0[s2 + 3][t] = f0.w;
            sX1[s2 + 0][t] = f1.x; sX1[s2 + 1][t] = f1.y;
            sX1[s2 + 2][t] = f1.z; sX1[s2 + 3][t] = f1.w;
        }
        __syncthreads();
        const ulonglong2* gp = (const ulonglong2*)(sG + (s1 << 8));
#pragma unroll
        for (int s2 = 0; s2 < 16; s2++) {
            float v0 = sX0[s2][tid];
            float v1 = sX1[s2][tid];
            unsigned long long vv0 = pack2(v0, v0);
            unsigned long long vv1 = pack2(v1, v1);
#pragma unroll
            for (int q = 0; q < 4; q++) {
                ulonglong2 g = gp[(s2 << 2) + q];
                fma2(acc0[(q << 1)    ], vv0, g.x);
                fma2(acc0[(q << 1) + 1], vv0, g.y);
                fma2(acc1[(q << 1)    ], vv1, g.x);
                fma2(acc1[(q << 1) + 1], vv1, g.y);
            }
        }
        __syncthreads();
    }

    // epilogue: unpack, add bias, store y, reduce GroupNorm partials
    float y0[16], y1[16];
#pragma unroll
    for (int q = 0; q < 8; q++) {
        unpack2(acc0[q], y0[2 * q], y0[2 * q + 1]);
        unpack2(acc1[q], y1[2 * q], y1[2 * q + 1]);
    }
#pragma unroll
    for (int e = 0; e < 16; e++) { float g0v = sg0[e]; y0[e] += g0v; y1[e] += g0v; }

    const size_t ybase = (((size_t)b) << 18) + (((size_t)hp) << 8) + tid;
#pragma unroll
    for (int e = 0; e < 16; e++) {
        g_Y[ybase + ((size_t)e << 14)]       = y0[e];
        g_Y[ybase + ((size_t)e << 14) + 128] = y1[e];
    }

    float gs[8], gq[8];
#pragma unroll
    for (int g = 0; g < 8; g++) {
        float a = y0[2 * g], bb = y0[2 * g + 1], c = y1[2 * g], d = y1[2 * g + 1];
        gs[g] = a + bb + c + d;
        gq[g] = a * a + bb * bb + c * c + d * d;
    }
#pragma unroll
    for (int off = 16; off; off >>= 1) {
#pragma unroll
        for (int g = 0; g < 8; g++) {
            gs[g] += __shfl_down_sync(0xffffffffu, gs[g], off);
            gq[g] += __shfl_down_sync(0xffffffffu, gq[g], off);
        }
    }
    const int lane = tid & 31, w = tid >> 5;
    if (lane == 0) {
#pragma unroll
        for (int g = 0; g < 8; g++) { sred[w][g] = gs[g]; sred[w][8 + g] = gq[g]; }
    }
    __syncthreads();
    if (tid < 16) {
        float s = sred[0][tid] + sred[1][tid] + sred[2][tid] + sred[3][tid];
        if (tid < 8) g_psum[(b * 8 + tid) * 64 + hp] = s;        // deterministic slot
        else         g_psq[(b * 8 + tid - 8) * 64 + hp] = s;
    }
}

// ---------------------------------------------------------------------------
// Kernel 3: reduce 64 per-block partials per (batch,group) -> mean, invstd.
// ---------------------------------------------------------------------------
__global__ void stats_kernel() {
    const int bg = threadIdx.x;          // 64 threads
    float s = 0.f, q = 0.f;
    for (int k = 0; k < 64; k++) { s += g_psum[bg * 64 + k]; q += g_psq[bg * 64 + k]; }
    const float invN = 1.0f / 32768.0f;  // 2 channels * 128 * 128
    float mean = s * invN;
    float var  = q * invN - mean * mean;
    g_mean[bg] = mean;
    g_istd[bg] = rsqrtf(var + 1e-5f);
}

// ---------------------------------------------------------------------------
// Kernel 4: normalize + affine, streaming float4.
// ---------------------------------------------------------------------------
__global__ void finalize_kernel(const float* __restrict__ gamma,
                                const float* __restrict__ beta,
                                float* __restrict__ out) {
    const int idx = blockIdx.x * blockDim.x + threadIdx.x;   // 524288 float4
    float4 v = ((const float4*)g_Y)[idx];
    const int plane = idx >> 12;          // 4096 float4 per (b,e) plane
    const int e = plane & 15, b = plane >> 4;
    const int bg = b * 8 + (e >> 1);
    const float is = g_istd[bg];
    const float sc = is * gamma[e];
    const float sh = beta[e] - g_mean[bg] * sc;
    v.x = v.x * sc + sh; v.y = v.y * sc + sh;
    v.z = v.z * sc + sh; v.w = v.w * sc + sh;
    ((float4*)out)[idx] = v;
}

extern "C" void kernel_launch(void* const* d_in, const int* in_sizes, int n_in,
                              void* d_out, int out_size) {
    const float* x     = (const float*)d_in[0];
    const float* wr    = (const float*)d_in[1];
    const float* wi    = (const float*)d_in[2];
    const float* br    = (const float*)d_in[3];
    const float* bi    = (const float*)d_in[4];
    const float* cw    = (const float*)d_in[5];
    const float* cb    = (const float*)d_in[6];
    const float* gamma = (const float*)d_in[7];
    const float* beta  = (const float*)d_in[8];
    float* out = (float*)d_out;

    precompute_kernel<<<16, 256>>>(wr, wi, br, bi, cw, cb);
    main_kernel<<<512, 128>>>(x);
    stats_kernel<<<1, 64>>>();
    finalize_kernel<<<2048, 256>>>(gamma, beta, out);
}

// round 2
// speedup vs baseline: 1.1821x; 1.1821x over previous
#include <cuda_runtime.h>
#include <math.h>

// ---------------------------------------------------------------------------
// CFNO: patchify(16x16) -> FFT(256,ortho) -> complex linear(256->16) ->
//       IFFT(16,ortho).real -> 1x1 conv(16->16) -> GroupNorm(8,16)
//
// Linear chain folded into one real [256,16] matrix G + bias g0 (device
// precompute). Hot pass: y = p @ G + g0, direct gmem->register streaming
// (image rows are already patch-major), no smem X tile, no mainloop barriers.
// ---------------------------------------------------------------------------

#define PI_D 3.141592653589793238462643383279502884

__device__ float g_G[4096];               // [256][16]
__device__ float g_g0[16];
__device__ float g_Y[8 * 16 * 128 * 128]; // 8 MB, (b,e,h,w)
__device__ float g_psum[64 * 128];        // [b*8+g][block-in-batch]
__device__ float g_psq[64 * 128];
__device__ float g_mean[64];
__device__ float g_istd[64];

// ---- packed fp32x2 helpers ----
__device__ __forceinline__ unsigned long long pack2(float a, float b) {
    unsigned long long r;
    asm("mov.b64 %0, {%1, %2};" : "=l"(r) : "f"(a), "f"(b));
    return r;
}
__device__ __forceinline__ void unpack2(unsigned long long v, float& lo, float& hi) {
    asm("mov.b64 {%0, %1}, %2;" : "=f"(lo), "=f"(hi) : "l"(v));
}
__device__ __forceinline__ void fma2(unsigned long long& acc,
                                     unsigned long long a, unsigned long long b) {
    asm("fma.rn.f32x2 %0, %1, %2, %0;" : "+l"(acc) : "l"(a), "l"(b));
}

// ---------------------------------------------------------------------------
// Kernel 1: fold FFT + complex linear + IFFT.real + conv into G, g0.
// ---------------------------------------------------------------------------
__global__ void precompute_kernel(const float* __restrict__ wr, const float* __restrict__ wi,
                                  const float* __restrict__ br, const float* __restrict__ bi,
                                  const float* __restrict__ cw, const float* __restrict__ cb) {
    __shared__ float cosT[256], sinT[256];
    __shared__ float swr[16 * 257], swi[16 * 257];
    __shared__ float sCR[256], sCI[256];
    __shared__ float sMR[256], sMI[256];
    const int tid = threadIdx.x;

    {
        double s, c;
        sincos(2.0 * PI_D * (double)tid / 256.0, &s, &c);
        cosT[tid] = (float)c; sinT[tid] = (float)s;
    }
    for (int i = tid; i < 4096; i += 256) {
        int d = i >> 8, k = i & 255;
        swr[d * 257 + k] = wr[i];
        swi[d * 257 + k] = wi[i];
    }
    __syncthreads();

    const int hi4 = tid >> 4, lo4 = tid & 15;
    {   // CR/CI: d = hi4, e = lo4
        float cr = 0.f, ci = 0.f;
#pragma unroll
        for (int m = 0; m < 16; m++) {
            int t = ((hi4 * m) & 15) << 4;
            float w = cw[lo4 * 16 + m];
            cr += w * cosT[t];
            ci += w * sinT[t];
        }
        sCR[hi4 * 16 + lo4] = cr; sCI[hi4 * 16 + lo4] = ci;
    }
    {   // MR/MI: jl = hi4, d = lo4
        const int jl = hi4, d = lo4;
        const int j = (blockIdx.x << 4) + jl;
        const float* a  = swr + d * 257;
        const float* bb = swi + d * 257;
        float mr = 0.f, mi = 0.f;
        int t = 0;
        for (int k = 0; k < 256; k++) {
            float c = cosT[t], s = sinT[t];
            float av = a[k], bv = bb[k];
            mr += av * c + bv * s;
            mi += bv * c - av * s;
            t = (t + j) & 255;
        }
        sMR[jl * 16 + d] = mr; sMI[jl * 16 + d] = mi;
    }
    __syncthreads();
    {   // G[j][e]
        const int jl = hi4, e = lo4;
        const int j = (blockIdx.x << 4) + jl;
        float g = 0.f;
#pragma unroll
        for (int d = 0; d < 16; d++)
            g += sMR[jl * 16 + d] * sCR[d * 16 + e] - sMI[jl * 16 + d] * sCI[d * 16 + e];
        g_G[j * 16 + e] = g * (1.0f / 64.0f);
    }
    if (blockIdx.x == 0 && tid < 16) {
        float acc = cb[tid];
        for (int m = 0; m < 16; m++) {
            float b0 = 0.f;
            for (int d = 0; d < 16; d++) {
                int t = ((d * m) & 15) << 4;
                b0 += br[d] * cosT[t] - bi[d] * sinT[t];
            }
            acc += cw[tid * 16 + m] * b0 * 0.25f;
        }
        g_g0[tid] = acc;
    }
}

// ---------------------------------------------------------------------------
// Kernel 2 (hot): direct-streaming GEMM. Grid 1024 x 64 threads.
// Block = (batch b, patch-pair-row hp, w-half wh). Thread owns patches
// (2hp, w) and (2hp+1, w) with w = 64*wh + tid. Per s1 step it loads each
// patch's 16 contiguous floats (4x LDG.128) and FMAs against the broadcast
// G slice from smem. Register ping-pong hides gmem latency.
// ---------------------------------------------------------------------------
__device__ __forceinline__ void compute_step(const float* sG, int s1,
                                             const float4* A, const float4* B,
                                             unsigned long long* acc0,
                                             unsigned long long* acc1) {
    float xa[16], xc[16];
#pragma unroll
    for (int q = 0; q < 4; q++) {
        xa[4 * q + 0] = A[q].x; xa[4 * q + 1] = A[q].y;
        xa[4 * q + 2] = A[q].z; xa[4 * q + 3] = A[q].w;
        xc[4 * q + 0] = B[q].x; xc[4 * q + 1] = B[q].y;
        xc[4 * q + 2] = B[q].z; xc[4 * q + 3] = B[q].w;
    }
    const ulonglong2* gp = (const ulonglong2*)(sG + (s1 << 8));
#pragma unroll
    for (int s2 = 0; s2 < 16; s2++) {
        unsigned long long va = pack2(xa[s2], xa[s2]);
        unsigned long long vc = pack2(xc[s2], xc[s2]);
#pragma unroll
        for (int q = 0; q < 4; q++) {
            ulonglong2 g = gp[(s2 << 2) + q];
            fma2(acc0[(q << 1)    ], va, g.x);
            fma2(acc0[(q << 1) + 1], va, g.y);
            fma2(acc1[(q << 1)    ], vc, g.x);
            fma2(acc1[(q << 1) + 1], vc, g.y);
        }
    }
}

__global__ void __launch_bounds__(64) main_kernel(const float* __restrict__ x) {
    __shared__ __align__(16) float sG[4096];
    __shared__ float sg0[16];
    __shared__ float sred[2][16];
    const int tid = threadIdx.x;
    const int pr  = blockIdx.x;            // 0..1023
    const int b   = pr >> 7;
    const int sub = pr & 127;
    const int hp  = sub >> 1;              // 0..63 (pair of patch rows)
    const int wh  = sub & 1;               // 0/1 w-half

    {
        const float4* g4 = (const float4*)g_G;
        float4* s4 = (float4*)sG;
        for (int i = tid; i < 1024; i += 64) s4[i] = g4[i];
        if (tid < 16) sg0[tid] = g_g0[tid];
    }
    __syncthreads();

    // patch A rows: 32*hp + s1 ; patch B rows: 32*hp + 16 + s1
    const float* xb = x + (((size_t)b) << 22) + (((size_t)hp) << 16)
                        + (size_t)(((wh << 6) + tid) << 4);

    unsigned long long acc0[8], acc1[8];
#pragma unroll
    for (int i = 0; i < 8; i++) { acc0[i] = 0ull; acc1[i] = 0ull; }

    float4 bufA0[4], bufB0[4], bufA1[4], bufB1[4];
    {
        const float4* rA = (const float4*)(xb);
        const float4* rB = (const float4*)(xb + (16 << 11));
#pragma unroll
        for (int q = 0; q < 4; q++) { bufA0[q] = rA[q]; bufB0[q] = rB[q]; }
    }
#pragma unroll
    for (int s1 = 0; s1 < 16; s1 += 2) {
        {   // prefetch s1+1
            const float4* rA = (const float4*)(xb + ((s1 + 1) << 11));
            const float4* rB = (const float4*)(xb + ((s1 + 17) << 11));
#pragma unroll
            for (int q = 0; q < 4; q++) { bufA1[q] = rA[q]; bufB1[q] = rB[q]; }
        }
        compute_step(sG, s1, bufA0, bufB0, acc0, acc1);
        if (s1 + 2 < 16) {   // prefetch s1+2
            const float4* rA = (const float4*)(xb + ((s1 + 2) << 11));
            const float4* rB = (const float4*)(xb + ((s1 + 18) << 11));
#pragma unroll
            for (int q = 0; q < 4; q++) { bufA0[q] = rA[q]; bufB0[q] = rB[q]; }
        }
        compute_step(sG, s1 + 1, bufA1, bufB1, acc0, acc1);
    }

    // epilogue
    float y0[16], y1[16];
#pragma unroll
    for (int q = 0; q < 8; q++) {
        unpack2(acc0[q], y0[2 * q], y0[2 * q + 1]);
        unpack2(acc1[q], y1[2 * q], y1[2 * q + 1]);
    }
#pragma unroll
    for (int e = 0; e < 16; e++) { float g0v = sg0[e]; y0[e] += g0v; y1[e] += g0v; }

    // g_Y layout (b,e,h,w): h0 = 2hp (A), 2hp+1 (B), w = 64*wh + tid
    const size_t ybase = (((size_t)b) << 18) + (((size_t)hp) << 8) + (wh << 6) + tid;
#pragma unroll
    for (int e = 0; e < 16; e++) {
        g_Y[ybase + ((size_t)e << 14)]       = y0[e];
        g_Y[ybase + ((size_t)e << 14) + 128] = y1[e];
    }

    // GroupNorm partials
    float gs[8], gq[8];
#pragma unroll
    for (int g = 0; g < 8; g++) {
        float a = y0[2 * g], c = y0[2 * g + 1], d = y1[2 * g], f = y1[2 * g + 1];
        gs[g] = a + c + d + f;
        gq[g] = a * a + c * c + d * d + f * f;
    }
#pragma unroll
    for (int off = 16; off; off >>= 1) {
#pragma unroll
        for (int g = 0; g < 8; g++) {
            gs[g] += __shfl_down_sync(0xffffffffu, gs[g], off);
            gq[g] += __shfl_down_sync(0xffffffffu, gq[g], off);
        }
    }
    const int lane = tid & 31, w = tid >> 5;
    if (lane == 0) {
#pragma unroll
        for (int g = 0; g < 8; g++) { sred[w][g] = gs[g]; sred[w][8 + g] = gq[g]; }
    }
    __syncthreads();
    if (tid < 16) {
        float s = sred[0][tid] + sred[1][tid];
        if (tid < 8) g_psum[(b * 8 + tid) * 128 + sub] = s;
        else         g_psq[(b * 8 + tid - 8) * 128 + sub] = s;
    }
}

// ---------------------------------------------------------------------------
// Kernel 3: reduce 128 partials per (batch,group). 512 threads, 8 per bg.
// ---------------------------------------------------------------------------
__global__ void stats_kernel() {
    const int tid = threadIdx.x;
    const int bg = tid >> 3, k = tid & 7;
    float s = 0.f, q = 0.f;
#pragma unroll
    for (int i = 0; i < 16; i++) {
        s += g_psum[bg * 128 + k + (i << 3)];
        q += g_psq[bg * 128 + k + (i << 3)];
    }
#pragma unroll
    for (int off = 4; off; off >>= 1) {
        s += __shfl_down_sync(0xffffffffu, s, off, 8);
        q += __shfl_down_sync(0xffffffffu, q, off, 8);
    }
    if (k == 0) {
        const float invN = 1.0f / 32768.0f;
        float mean = s * invN;
        float var  = q * invN - mean * mean;
        g_mean[bg] = mean;
        g_istd[bg] = rsqrtf(var + 1e-5f);
    }
}

// ---------------------------------------------------------------------------
// Kernel 4: normalize + affine; 4 float4 per thread for MLP.
// ---------------------------------------------------------------------------
__global__ void finalize_kernel(const float* __restrict__ gamma,
                                const float* __restrict__ beta,
                                float* __restrict__ out) {
    const int t = blockIdx.x * blockDim.x + threadIdx.x;  // 131072 threads
#pragma unroll
    for (int r = 0; r < 4; r++) {
        const int idx = t + (r << 17);
        float4 v = ((const float4*)g_Y)[idx];
        const int plane = idx >> 12;          // 4096 float4 per (b,e) plane
        const int e = plane & 15, b = plane >> 4;
        const int bg = b * 8 + (e >> 1);
        const float is = g_istd[bg];
        const float sc = is * gamma[e];
        const float sh = beta[e] - g_mean[bg] * sc;
        v.x = v.x * sc + sh; v.y = v.y * sc + sh;
        v.z = v.z * sc + sh; v.w = v.w * sc + sh;
        ((float4*)out)[idx] = v;
    }
}

extern "C" void kernel_launch(void* const* d_in, const int* in_sizes, int n_in,
                              void* d_out, int out_size) {
    const float* x     = (const float*)d_in[0];
    const float* wr    = (const float*)d_in[1];
    const float* wi    = (const float*)d_in[2];
    const float* br    = (const float*)d_in[3];
    const float* bi    = (const float*)d_in[4];
    const float* cw    = (const float*)d_in[5];
    const float* cb    = (const float*)d_in[6];
    const float* gamma = (const float*)d_in[7];
    const float* beta  = (const float*)d_in[8];
    float* out = (float*)d_out;

    precompute_kernel<<<16, 256>>>(wr, wi, br, bi, cw, cb);
    main_kernel<<<1024, 64>>>(x);
    stats_kernel<<<1, 512>>>();
    finalize_kernel<<<512, 256>>>(gamma, beta, out);
}